// round 13
// baseline (speedup 1.0000x reference)
#include <cuda_runtime.h>
#include <cuda_pipeline.h>

// ---------------- problem dims (fixed by the dataset) ----------------
#define BATCH   2
#define C_IN    256
#define HH      40
#define WW      40
#define CMID    64     // compressed channels
#define CK      100    // k2 * S^2 encoder output channels
#define KK      25     // k2
#define HPAD    44     // xT padded (halo 2)
#define CPH     42     // comp padded (halo 1)

typedef unsigned long long u64;

__device__ __forceinline__ u64 dup2f(float x) {
    u64 r; asm("mov.b64 %0,{%1,%1};" : "=l"(r) : "f"(x)); return r;
}
__device__ __forceinline__ void fma2(u64& d, u64 a, u64 b) {
    asm("fma.rn.f32x2 %0,%1,%2,%0;" : "+l"(d) : "l"(a), "l"(b));
}

// ---------------- scratch (zero-initialized at module load; halos stay 0) ----------------
__device__ __align__(16) float g_xT  [BATCH * HPAD * HPAD * C_IN];   // x NHWC, 2-px zero halo
__device__ __align__(16) float g_comp[BATCH * CPH  * CPH  * CMID];   // compressed NHWC, 1-px halo
__device__ __align__(16) float g_kern[BATCH * HH * WW * CK];         // encoder conv out, NHWC
__device__ __align__(16) float g_wt  [9 * CMID * CK];                // w_enc transposed [tap][ci][o]

// ---------------- stage A: 1x1 GEMM (o-split halves, register-pipelined x) + xpose + wenc prep --
// blocks 0..199: GEMM — tile = blk>>1 (32 px), half = blk&1 (32 outs). 200..424: wenc prep.
#define WS_STRIDE 36
#define XS_STRIDE 33
#define SMEM_A_BYTES ((C_IN * WS_STRIDE + 64 * XS_STRIDE) * (int)sizeof(float))

__global__ void stageA_compress(const float* __restrict__ x,
                                const float* __restrict__ wcomp,
                                const float* __restrict__ wenc) {
    extern __shared__ float sm[];
    float* w_s = sm;                       // [c 256][o_local 32] stride 36 (16B-aligned reads)
    float* x_s = sm + C_IN * WS_STRIDE;    // [c_l 64][pix 32] stride 33

    const int t   = threadIdx.x;
    const int blk = blockIdx.x;

    if (blk >= 200) {                      // w_enc transpose: (100,64,3,3) -> [tap][ci][o]
        int i = (blk - 200) * 256 + t;
        if (i < 9 * CMID * CK) {
            int tap  = i / (CMID * CK);
            int rest = i % (CMID * CK);
            int ci   = rest / CK;
            int o    = rest % CK;
            g_wt[i] = wenc[o * (CMID * 9) + ci * 9 + tap];
        }
        return;
    }

    const int tile = blk >> 1;
    const int half = blk & 1;              // output-channel half (o 0..31 or 32..63)
    const int b    = tile / 50;
    const int pix0 = (tile % 50) * 32;
    const int ob   = half * 32;

    const int cl_ld = t >> 5;              // channel-local row this thread loads
    const int pl_ld = t & 31;              // pixel-local col this thread loads

    // ---- preload x chunk 0 into registers (latency hides under weight load) ----
    float xr[8];
    #pragma unroll
    for (int r = 0; r < 8; r++)
        xr[r] = x[(size_t)(b * C_IN + cl_ld + r * 8) * (HH * WW) + pix0 + pl_ld];

    // ---- load this half of w_comp (32 o x 256 c), transposed to [c][o_local] ----
    // i = t + iter*256: o_local = i>>8, c = i&255 -> coalesced LDG along c
    for (int i = t; i < 32 * C_IN; i += 256) {
        int o = i >> 8, c = i & 255;
        w_s[c * WS_STRIDE + o] = wcomp[(ob + o) * C_IN + c];
    }

    u64 acc0 = 0, acc1 = 0;
    const int pix_l = t & 31;              // warp spans 32 pixels (x coalesced)
    const int o0    = (t >> 5) << 2;       // 4 consecutive outputs (warp shares o0 -> broadcast)

    for (int k = 0; k < 4; k++) {
        const int c0 = k * 64;
        __syncthreads();                   // x_s free (prev chunk consumed); iter0: no-op
        #pragma unroll
        for (int r = 0; r < 8; r++)
            x_s[(cl_ld + r * 8) * XS_STRIDE + pl_ld] = xr[r];
        __syncthreads();                   // x_s ready (also fences w_s on iter0)

        // issue next chunk's loads NOW — latency hidden behind emit + GEMM below
        if (k < 3) {
            #pragma unroll
            for (int r = 0; r < 8; r++)
                xr[r] = x[(size_t)(b * C_IN + c0 + 64 + cl_ld + r * 8) * (HH * WW) + pix0 + pl_ld];
        }

        // emit transposed x to g_xT (half 0 only; coalesced along channels)
        if (half == 0) {
            #pragma unroll
            for (int r = 0; r < 8; r++) {
                int idx = t + r * 256;
                int cl = idx & 63, pl = idx >> 6;
                int pix = pix0 + pl;
                int hs = pix / WW, ws = pix % WW;
                g_xT[((size_t)(b * HPAD + hs + 2) * HPAD + (ws + 2)) * C_IN + c0 + cl] =
                    x_s[cl * XS_STRIDE + pl];
            }
        }
        // GEMM chunk
        #pragma unroll 16
        for (int c = 0; c < 64; c++) {
            float xv = x_s[c * XS_STRIDE + pix_l];
            u64 xx = dup2f(xv);
            ulonglong2 w = *(const ulonglong2*)&w_s[(c0 + c) * WS_STRIDE + o0];
            fma2(acc0, xx, w.x);
            fma2(acc1, xx, w.y);
        }
    }

    const int pix = pix0 + pix_l;
    const int hs = pix / WW, ws = pix % WW;
    float* dst = &g_comp[((size_t)(b * CPH + hs + 1) * CPH + (ws + 1)) * CMID + ob + o0];
    *(ulonglong2*)dst = make_ulonglong2(acc0, acc1);
}

// ---------------- stage B (R2 verbatim): 3x3 encoder conv (64 -> 100 ch) ----------------
#define CS_STRIDE 66
#define B_WBUF    (CMID * CK)                 // 6400 floats per tap
#define SMEM_B_BYTES ((2 * B_WBUF + 48 * CS_STRIDE) * (int)sizeof(float))

__global__ void __launch_bounds__(128) stageB_encoder() {
    extern __shared__ float smB[];
    float* wbuf   = smB;                       // [2][6400]
    float* comp_s = smB + 2 * B_WBUF;          // [48 px][66]

    const int t   = threadIdx.x;
    const int blk = blockIdx.x;
    const int b   = blk / 80;
    const int rem = blk % 80;
    const int h0  = (rem / 4) * 2;
    const int ws0 = (rem % 4) * 10;

    for (int i = t; i < 48 * CMID; i += 128) {
        int pxl = i >> 6, ci = i & 63;
        comp_s[pxl * CS_STRIDE + ci] =
            g_comp[((size_t)(b * CPH + h0 + pxl / 12) * CPH + ws0 + pxl % 12) * CMID + ci];
    }

    for (int i = t; i < B_WBUF / 4; i += 128)
        __pipeline_memcpy_async(&wbuf[i * 4], &g_wt[i * 4], 16);
    __pipeline_commit();

    const int og  = t / 5;          // 0..24 (t<125 active)
    const int pxg = t % 5;
    const bool active = (t < 125);

    u64 a00 = 0, a01 = 0, a10 = 0, a11 = 0;   // row0 col0/col1: {o0,o1},{o2,o3} packed per px
    u64 b00 = 0, b01 = 0, b10 = 0, b11 = 0;   // row1

    for (int tap = 0; tap < 9; tap++) {
        if (tap < 8) {
            float* dst = &wbuf[((tap + 1) & 1) * B_WBUF];
            const float* src = &g_wt[(tap + 1) * B_WBUF];
            for (int i = t; i < B_WBUF / 4; i += 128)
                __pipeline_memcpy_async(&dst[i * 4], &src[i * 4], 16);
            __pipeline_commit();
            __pipeline_wait_prior(1);
        } else {
            __pipeline_wait_prior(0);
        }
        __syncthreads();

        if (active) {
            const float* ws = &wbuf[(tap & 1) * B_WBUF];
            const int dh = tap / 3, dw = tap % 3;
            const float* p00 = &comp_s[(dh * 12 + 2 * pxg + dw) * CS_STRIDE];
            const float* p01 = p00 + CS_STRIDE;
            const float* p10 = p00 + 12 * CS_STRIDE;
            const float* p11 = p10 + CS_STRIDE;
            #pragma unroll 8
            for (int ci = 0; ci < CMID; ci += 2) {
                float2 x00 = *(const float2*)&p00[ci];
                float2 x01 = *(const float2*)&p01[ci];
                float2 x10 = *(const float2*)&p10[ci];
                float2 x11 = *(const float2*)&p11[ci];
                ulonglong2 w0 = *(const ulonglong2*)&ws[ci * CK + og * 4];
                ulonglong2 w1 = *(const ulonglong2*)&ws[(ci + 1) * CK + og * 4];
                u64 d;
                d = dup2f(x00.x); fma2(a00, d, w0.x); fma2(a01, d, w0.y);
                d = dup2f(x01.x); fma2(a10, d, w0.x); fma2(a11, d, w0.y);
                d = dup2f(x10.x); fma2(b00, d, w0.x); fma2(b01, d, w0.y);
                d = dup2f(x11.x); fma2(b10, d, w0.x); fma2(b11, d, w0.y);
                d = dup2f(x00.y); fma2(a00, d, w1.x); fma2(a01, d, w1.y);
                d = dup2f(x01.y); fma2(a10, d, w1.x); fma2(a11, d, w1.y);
                d = dup2f(x10.y); fma2(b00, d, w1.x); fma2(b01, d, w1.y);
                d = dup2f(x11.y); fma2(b10, d, w1.x); fma2(b11, d, w1.y);
            }
        }
        __syncthreads();
    }

    if (active) {
        const int c0 = ws0 + 2 * pxg;
        float* r0 = &g_kern[((size_t)(b * HH + h0) * WW + c0) * CK + og * 4];
        float* r1 = &g_kern[((size_t)(b * HH + h0 + 1) * WW + c0) * CK + og * 4];
        *(ulonglong2*)(r0)      = make_ulonglong2(a00, a01);
        *(ulonglong2*)(r0 + CK) = make_ulonglong2(a10, a11);
        *(ulonglong2*)(r1)      = make_ulonglong2(b00, b01);
        *(ulonglong2*)(r1 + CK) = make_ulonglong2(b10, b11);
    }
}

// ---------------- stage C (R7 verbatim): sliding-window reassembly, coalesced stores ----------
#define ST_STRIDE 24

__global__ void __launch_bounds__(256) stageC_reassemble(float* __restrict__ out) {
    __shared__ float4 sk[5][KK];            // softmax weights per px
    __shared__ float  st[256 * ST_STRIDE];  // [ch][20+pad] output staging

    const int t   = threadIdx.x;
    const int blk = blockIdx.x;
    const int b   = blk / 320;
    const int p0  = (blk % 320) * 5;

    const int hu    = p0 / 20, pm0 = p0 % 20;
    const int hsrc  = p0 / WW, wsrc0 = p0 % WW;   // shared by all 5 px (wsrc_i = wsrc0+i)
    const int wid = t >> 5, lane = t & 31;

    // ---- window loads: 5 rows x 9 cols, all issued up front ----
    const float* xb = &g_xT[((size_t)(b * HPAD + hsrc) * HPAD + wsrc0) * C_IN + t];
    float xw[45];
    #pragma unroll
    for (int r = 0; r < 5; r++)
        #pragma unroll
        for (int c = 0; c < 9; c++)
            xw[r * 9 + c] = xb[(r * HPAD + c) * C_IN];

    // ---- 20 softmaxes (5 px x 4 subpx), 8 warps loop ----
    const int hc = hu >> 1, sh = hu & 1;
    for (int s = wid; s < 20; s += 8) {
        const int px = s >> 2, d = s & 3;
        const int wc = 2 * (pm0 + px) + (d >> 1), sw = d & 1;
        float v = -3.0e38f;
        if (lane < KK)
            v = g_kern[((size_t)(b * HH + hc) * WW + wc) * CK + lane * 4 + sh * 2 + sw];
        float m = v;
        #pragma unroll
        for (int off = 16; off; off >>= 1)
            m = fmaxf(m, __shfl_xor_sync(0xffffffffu, m, off));
        float e = (lane < KK) ? __expf(v - m) : 0.f;
        float su = e;
        #pragma unroll
        for (int off = 16; off; off >>= 1)
            su += __shfl_xor_sync(0xffffffffu, su, off);
        if (lane < KK)
            ((float*)&sk[px][lane])[d] = e / su;
    }
    __syncthreads();

    // ---- per-px FMA, results to staging ----
    #pragma unroll
    for (int i = 0; i < 5; i++) {
        const ulonglong2* skp = (const ulonglong2*)&sk[i][0];
        u64 a01 = 0, a23 = 0;
        #pragma unroll
        for (int k = 0; k < 25; k++) {
            u64 xx = dup2f(xw[(k / 5) * 9 + i + (k % 5)]);
            ulonglong2 w = skp[k];
            fma2(a01, xx, w.x);
            fma2(a23, xx, w.y);
        }
        *(u64*)&st[t * ST_STRIDE + i * 4]     = a01;
        *(u64*)&st[t * ST_STRIDE + i * 4 + 2] = a23;
    }
    __syncthreads();

    // ---- coalesced store: thread = (ch, wu-quad), warp covers consecutive wu ----
    const size_t obase = ((size_t)(b * C_IN) * (2 * HH) + hu) * (2 * WW) + pm0 * 4;
    #pragma unroll
    for (int j = 0; j < 5; j++) {
        int f  = t + j * 256;          // 0..1279
        int ch = f / 5, w4 = f % 5;
        float4 v = *(const float4*)&st[ch * ST_STRIDE + w4 * 4];
        *(float4*)&out[obase + (size_t)ch * (4 * HH * WW) + w4 * 4] = v;
    }
}

// ---------------- launch ----------------
extern "C" void kernel_launch(void* const* d_in, const int* in_sizes, int n_in,
                              void* d_out, int out_size) {
    const float* x     = (const float*)d_in[0];
    const float* wcomp = (const float*)d_in[1];
    const float* wenc  = (const float*)d_in[2];
    float* out = (float*)d_out;

    cudaFuncSetAttribute(stageA_compress,
                         cudaFuncAttributeMaxDynamicSharedMemorySize, SMEM_A_BYTES);
    cudaFuncSetAttribute(stageB_encoder,
                         cudaFuncAttributeMaxDynamicSharedMemorySize, SMEM_B_BYTES);

    stageA_compress<<<200 + (9 * CMID * CK + 255) / 256, 256, SMEM_A_BYTES>>>(x, wcomp, wenc);
    stageB_encoder<<<160, 128, SMEM_B_BYTES>>>();
    stageC_reassemble<<<640, 256>>>(out);
}

// round 14
// speedup vs baseline: 1.0741x; 1.0741x over previous
#include <cuda_runtime.h>
#include <cuda_pipeline.h>

// ---------------- problem dims (fixed by the dataset) ----------------
#define BATCH   2
#define C_IN    256
#define HH      40
#define WW      40
#define CMID    64     // compressed channels
#define CK      100    // k2 * S^2 encoder output channels
#define KK      25     // k2
#define HPAD    44     // xT padded (halo 2)
#define CPH     42     // comp padded (halo 1)
#define PST     (BATCH * CPH * CPH * CMID)   // one K-partial buffer (225792 floats)

typedef unsigned long long u64;

__device__ __forceinline__ u64 dup2f(float x) {
    u64 r; asm("mov.b64 %0,{%1,%1};" : "=l"(r) : "f"(x)); return r;
}
__device__ __forceinline__ void fma2(u64& d, u64 a, u64 b) {
    asm("fma.rn.f32x2 %0,%1,%2,%0;" : "+l"(d) : "l"(a), "l"(b));
}

// ---------------- scratch (zero-initialized at module load; halos stay 0) ----------------
__device__ __align__(16) float g_xT   [BATCH * HPAD * HPAD * C_IN];  // x NHWC, 2-px zero halo
__device__ __align__(16) float g_compP[2 * PST];                     // 2 K-split partials, halo 1
__device__ __align__(16) float g_kern [BATCH * HH * WW * CK];        // encoder conv out, NHWC
__device__ __align__(16) float g_wt   [9 * CMID * CK];               // w_enc transposed [tap][ci][o]

// ---------------- stage A: 1x1 GEMM (K-split halves, register-pipelined x) + xpose + wenc prep --
// blocks 0..199: GEMM — tile = blk>>1 (32 px), kh = blk&1 (channels kh*128..+127).
// blocks 200..424: wenc transpose.
#define WS_STRIDE 68
#define XS_STRIDE 33
#define SMEM_A_BYTES ((128 * WS_STRIDE + 64 * XS_STRIDE) * (int)sizeof(float))

__global__ void stageA_compress(const float* __restrict__ x,
                                const float* __restrict__ wcomp,
                                const float* __restrict__ wenc) {
    extern __shared__ float sm[];
    float* w_s = sm;                       // [c_l 128][o 64] stride 68
    float* x_s = sm + 128 * WS_STRIDE;     // [c_l 64][pix 32] stride 33

    const int t   = threadIdx.x;
    const int blk = blockIdx.x;

    if (blk >= 200) {                      // w_enc transpose: (100,64,3,3) -> [tap][ci][o]
        int i = (blk - 200) * 256 + t;
        if (i < 9 * CMID * CK) {
            int tap  = i / (CMID * CK);
            int rest = i % (CMID * CK);
            int ci   = rest / CK;
            int o    = rest % CK;
            g_wt[i] = wenc[o * (CMID * 9) + ci * 9 + tap];
        }
        return;
    }

    const int tile  = blk >> 1;
    const int kh    = blk & 1;             // K half: input channels cbase..cbase+127
    const int b     = tile / 50;
    const int pix0  = (tile % 50) * 32;
    const int cbase = kh * 128;

    const int cl_ld = t >> 5;              // channel-local row this thread loads
    const int pl_ld = t & 31;              // pixel-local col this thread loads

    // ---- preload x chunk 0 into registers (latency hides under weight load) ----
    float xr[8];
    #pragma unroll
    for (int r = 0; r < 8; r++)
        xr[r] = x[(size_t)(b * C_IN + cbase + cl_ld + r * 8) * (HH * WW) + pix0 + pl_ld];

    // ---- load this K-half of w_comp (64 o x 128 c), transposed to [c_l][o] ----
    for (int i = t; i < CMID * 128; i += 256) {
        int o = i >> 7, cl = i & 127;      // coalesced LDG along cl
        w_s[cl * WS_STRIDE + o] = wcomp[o * C_IN + cbase + cl];
    }

    u64 acc[4] = {0ull, 0ull, 0ull, 0ull};
    const int pix_l = t & 31;              // warp spans 32 pixels (x coalesced)
    const int o0    = (t >> 5) << 3;       // warp shares o0 (w broadcast), 8 outputs

    for (int k = 0; k < 2; k++) {
        const int c0l = k * 64;            // local channel base within this K-half
        const int c0g = cbase + c0l;       // global channel base
        __syncthreads();                   // x_s free (prev chunk consumed); iter0: no-op
        #pragma unroll
        for (int r = 0; r < 8; r++)
            x_s[(cl_ld + r * 8) * XS_STRIDE + pl_ld] = xr[r];
        __syncthreads();                   // x_s ready (also fences w_s on iter0)

        // issue next chunk's loads NOW — latency hidden behind emit + GEMM below
        if (k < 1) {
            #pragma unroll
            for (int r = 0; r < 8; r++)
                xr[r] = x[(size_t)(b * C_IN + c0g + 64 + cl_ld + r * 8) * (HH * WW) + pix0 + pl_ld];
        }

        // emit transposed x to g_xT (each K-half emits its own channels; no duplication)
        #pragma unroll
        for (int r = 0; r < 8; r++) {
            int idx = t + r * 256;
            int cl = idx & 63, pl = idx >> 6;
            int pix = pix0 + pl;
            int hs = pix / WW, ws = pix % WW;
            g_xT[((size_t)(b * HPAD + hs + 2) * HPAD + (ws + 2)) * C_IN + c0g + cl] =
                x_s[cl * XS_STRIDE + pl];
        }
        // GEMM chunk
        #pragma unroll 16
        for (int c = 0; c < 64; c++) {
            float xv = x_s[c * XS_STRIDE + pix_l];
            u64 xx = dup2f(xv);
            ulonglong2 wa = *(const ulonglong2*)&w_s[(c0l + c) * WS_STRIDE + o0];
            ulonglong2 wb = *(const ulonglong2*)&w_s[(c0l + c) * WS_STRIDE + o0 + 4];
            fma2(acc[0], xx, wa.x); fma2(acc[1], xx, wa.y);
            fma2(acc[2], xx, wb.x); fma2(acc[3], xx, wb.y);
        }
    }

    const int pix = pix0 + pix_l;
    const int hs = pix / WW, ws = pix % WW;
    float* dst = &g_compP[(size_t)kh * PST +
                          ((size_t)(b * CPH + hs + 1) * CPH + (ws + 1)) * CMID + o0];
    *(ulonglong2*)(dst)     = make_ulonglong2(acc[0], acc[1]);
    *(ulonglong2*)(dst + 4) = make_ulonglong2(acc[2], acc[3]);
}

// ---------------- stage B (R2 + partial-sum tile load): 3x3 encoder conv (64 -> 100 ch) --------
#define CS_STRIDE 66
#define B_WBUF    (CMID * CK)                 // 6400 floats per tap
#define SMEM_B_BYTES ((2 * B_WBUF + 48 * CS_STRIDE) * (int)sizeof(float))

__global__ void __launch_bounds__(128) stageB_encoder() {
    extern __shared__ float smB[];
    float* wbuf   = smB;                       // [2][6400]
    float* comp_s = smB + 2 * B_WBUF;          // [48 px][66]

    const int t   = threadIdx.x;
    const int blk = blockIdx.x;
    const int b   = blk / 80;
    const int rem = blk % 80;
    const int h0  = (rem / 4) * 2;
    const int ws0 = (rem % 4) * 10;

    for (int i = t; i < 48 * CMID; i += 128) {
        int pxl = i >> 6, ci = i & 63;
        size_t gi = ((size_t)(b * CPH + h0 + pxl / 12) * CPH + ws0 + pxl % 12) * CMID + ci;
        comp_s[pxl * CS_STRIDE + ci] = g_compP[gi] + g_compP[PST + gi];
    }

    for (int i = t; i < B_WBUF / 4; i += 128)
        __pipeline_memcpy_async(&wbuf[i * 4], &g_wt[i * 4], 16);
    __pipeline_commit();

    const int og  = t / 5;          // 0..24 (t<125 active)
    const int pxg = t % 5;
    const bool active = (t < 125);

    u64 a00 = 0, a01 = 0, a10 = 0, a11 = 0;   // row0 col0/col1: {o0,o1},{o2,o3} packed per px
    u64 b00 = 0, b01 = 0, b10 = 0, b11 = 0;   // row1

    for (int tap = 0; tap < 9; tap++) {
        if (tap < 8) {
            float* dst = &wbuf[((tap + 1) & 1) * B_WBUF];
            const float* src = &g_wt[(tap + 1) * B_WBUF];
            for (int i = t; i < B_WBUF / 4; i += 128)
                __pipeline_memcpy_async(&dst[i * 4], &src[i * 4], 16);
            __pipeline_commit();
            __pipeline_wait_prior(1);
        } else {
            __pipeline_wait_prior(0);
        }
        __syncthreads();

        if (active) {
            const float* ws = &wbuf[(tap & 1) * B_WBUF];
            const int dh = tap / 3, dw = tap % 3;
            const float* p00 = &comp_s[(dh * 12 + 2 * pxg + dw) * CS_STRIDE];
            const float* p01 = p00 + CS_STRIDE;
            const float* p10 = p00 + 12 * CS_STRIDE;
            const float* p11 = p10 + CS_STRIDE;
            #pragma unroll 8
            for (int ci = 0; ci < CMID; ci += 2) {
                float2 x00 = *(const float2*)&p00[ci];
                float2 x01 = *(const float2*)&p01[ci];
                float2 x10 = *(const float2*)&p10[ci];
                float2 x11 = *(const float2*)&p11[ci];
                ulonglong2 w0 = *(const ulonglong2*)&ws[ci * CK + og * 4];
                ulonglong2 w1 = *(const ulonglong2*)&ws[(ci + 1) * CK + og * 4];
                u64 d;
                d = dup2f(x00.x); fma2(a00, d, w0.x); fma2(a01, d, w0.y);
                d = dup2f(x01.x); fma2(a10, d, w0.x); fma2(a11, d, w0.y);
                d = dup2f(x10.x); fma2(b00, d, w0.x); fma2(b01, d, w0.y);
                d = dup2f(x11.x); fma2(b10, d, w0.x); fma2(b11, d, w0.y);
                d = dup2f(x00.y); fma2(a00, d, w1.x); fma2(a01, d, w1.y);
                d = dup2f(x01.y); fma2(a10, d, w1.x); fma2(a11, d, w1.y);
                d = dup2f(x10.y); fma2(b00, d, w1.x); fma2(b01, d, w1.y);
                d = dup2f(x11.y); fma2(b10, d, w1.x); fma2(b11, d, w1.y);
            }
        }
        __syncthreads();
    }

    if (active) {
        const int c0 = ws0 + 2 * pxg;
        float* r0 = &g_kern[((size_t)(b * HH + h0) * WW + c0) * CK + og * 4];
        float* r1 = &g_kern[((size_t)(b * HH + h0 + 1) * WW + c0) * CK + og * 4];
        *(ulonglong2*)(r0)      = make_ulonglong2(a00, a01);
        *(ulonglong2*)(r0 + CK) = make_ulonglong2(a10, a11);
        *(ulonglong2*)(r1)      = make_ulonglong2(b00, b01);
        *(ulonglong2*)(r1 + CK) = make_ulonglong2(b10, b11);
    }
}

// ---------------- stage C (R7 verbatim): sliding-window reassembly, coalesced stores ----------
#define ST_STRIDE 24

__global__ void __launch_bounds__(256) stageC_reassemble(float* __restrict__ out) {
    __shared__ float4 sk[5][KK];            // softmax weights per px
    __shared__ float  st[256 * ST_STRIDE];  // [ch][20+pad] output staging

    const int t   = threadIdx.x;
    const int blk = blockIdx.x;
    const int b   = blk / 320;
    const int p0  = (blk % 320) * 5;

    const int hu    = p0 / 20, pm0 = p0 % 20;
    const int hsrc  = p0 / WW, wsrc0 = p0 % WW;   // shared by all 5 px (wsrc_i = wsrc0+i)
    const int wid = t >> 5, lane = t & 31;

    // ---- window loads: 5 rows x 9 cols, all issued up front ----
    const float* xb = &g_xT[((size_t)(b * HPAD + hsrc) * HPAD + wsrc0) * C_IN + t];
    float xw[45];
    #pragma unroll
    for (int r = 0; r < 5; r++)
        #pragma unroll
        for (int c = 0; c < 9; c++)
            xw[r * 9 + c] = xb[(r * HPAD + c) * C_IN];

    // ---- 20 softmaxes (5 px x 4 subpx), 8 warps loop ----
    const int hc = hu >> 1, sh = hu & 1;
    for (int s = wid; s < 20; s += 8) {
        const int px = s >> 2, d = s & 3;
        const int wc = 2 * (pm0 + px) + (d >> 1), sw = d & 1;
        float v = -3.0e38f;
        if (lane < KK)
            v = g_kern[((size_t)(b * HH + hc) * WW + wc) * CK + lane * 4 + sh * 2 + sw];
        float m = v;
        #pragma unroll
        for (int off = 16; off; off >>= 1)
            m = fmaxf(m, __shfl_xor_sync(0xffffffffu, m, off));
        float e = (lane < KK) ? __expf(v - m) : 0.f;
        float su = e;
        #pragma unroll
        for (int off = 16; off; off >>= 1)
            su += __shfl_xor_sync(0xffffffffu, su, off);
        if (lane < KK)
            ((float*)&sk[px][lane])[d] = e / su;
    }
    __syncthreads();

    // ---- per-px FMA, results to staging ----
    #pragma unroll
    for (int i = 0; i < 5; i++) {
        const ulonglong2* skp = (const ulonglong2*)&sk[i][0];
        u64 a01 = 0, a23 = 0;
        #pragma unroll
        for (int k = 0; k < 25; k++) {
            u64 xx = dup2f(xw[(k / 5) * 9 + i + (k % 5)]);
            ulonglong2 w = skp[k];
            fma2(a01, xx, w.x);
            fma2(a23, xx, w.y);
        }
        *(u64*)&st[t * ST_STRIDE + i * 4]     = a01;
        *(u64*)&st[t * ST_STRIDE + i * 4 + 2] = a23;
    }
    __syncthreads();

    // ---- coalesced store: thread = (ch, wu-quad), warp covers consecutive wu ----
    const size_t obase = ((size_t)(b * C_IN) * (2 * HH) + hu) * (2 * WW) + pm0 * 4;
    #pragma unroll
    for (int j = 0; j < 5; j++) {
        int f  = t + j * 256;          // 0..1279
        int ch = f / 5, w4 = f % 5;
        float4 v = *(const float4*)&st[ch * ST_STRIDE + w4 * 4];
        *(float4*)&out[obase + (size_t)ch * (4 * HH * WW) + w4 * 4] = v;
    }
}

// ---------------- launch ----------------
extern "C" void kernel_launch(void* const* d_in, const int* in_sizes, int n_in,
                              void* d_out, int out_size) {
    const float* x     = (const float*)d_in[0];
    const float* wcomp = (const float*)d_in[1];
    const float* wenc  = (const float*)d_in[2];
    float* out = (float*)d_out;

    cudaFuncSetAttribute(stageA_compress,
                         cudaFuncAttributeMaxDynamicSharedMemorySize, SMEM_A_BYTES);
    cudaFuncSetAttribute(stageB_encoder,
                         cudaFuncAttributeMaxDynamicSharedMemorySize, SMEM_B_BYTES);

    stageA_compress<<<200 + (9 * CMID * CK + 255) / 256, 256, SMEM_A_BYTES>>>(x, wcomp, wenc);
    stageB_encoder<<<160, 128, SMEM_B_BYTES>>>();
    stageC_reassemble<<<640, 256>>>(out);
}